// round 2
// baseline (speedup 1.0000x reference)
#include <cuda_runtime.h>
#include <cstdint>

#define NB 4
#define LSEQ 16384
#define CCH 64
#define CM 16
#define NH 4
#define HB 128
#define KCH 128           // chunks per group
#define JTOT (NH*LSEQ)    // 65536
#define NKEY 640
#define TILE 512
#define NTILE (JTOT/TILE) // 128

typedef unsigned long long ull;

// ---------------- device scratch ----------------
__device__ __align__(16) float g_xembed[NB][LSEQ][CM];   // 4 MB
__device__ __align__(16) float g_yembed[NB][LSEQ][CCH];  // 16 MB
__device__ float g_xnorm[NB][LSEQ];
__device__ float g_invn[NB][LSEQ];
__device__ int   g_codes[NB][JTOT];
__device__ int   g_perm[NB][JTOT];
__device__ int   g_tileHist[NB][NTILE][NKEY];
__device__ int   g_keyBase[NB][NKEY];
__device__ __align__(16) float g_ret[NB][JTOT][CCH];     // 64 MB
__device__ float g_bs[NB][JTOT];

// ---------------- helpers ----------------
__device__ __forceinline__ ull pk2(float a, float b){
    ull u; asm("mov.b64 %0,{%1,%2};" : "=l"(u) : "f"(a), "f"(b)); return u;
}
__device__ __forceinline__ void upk2(ull u, float& a, float& b){
    asm("mov.b64 {%0,%1},%2;" : "=f"(a), "=f"(b) : "l"(u));
}
__device__ __forceinline__ ull f2fma(ull a, ull b, ull c){
    ull d; asm("fma.rn.f32x2 %0,%1,%2,%3;" : "=l"(d) : "l"(a), "l"(b), "l"(c)); return d;
}
// exp(x) for x <= 0, FMA-pipe only (no MUFU), rel err ~2e-6
__device__ __forceinline__ float fexp(float x){
    float y = fmaxf(x * 1.4426950408889634f, -126.0f);
    int   e = __float2int_rn(y);
    float f = y - (float)e;
    float p = 0.0013333558f;
    p = fmaf(p, f, 0.0096181291f);
    p = fmaf(p, f, 0.0555041087f);
    p = fmaf(p, f, 0.2402264472f);
    p = fmaf(p, f, 0.6931472028f);
    p = fmaf(p, f, 1.0f);
    return p * __int_as_float((e + 127) << 23);
}

// ---------------- K1: embeddings ----------------
#define TL 64
__global__ void k_embed(const float* __restrict__ x, const float* __restrict__ wm,
                        const float* __restrict__ wa, const float* __restrict__ wb){
    __shared__ float sx[TL+2][64];
    __shared__ float swm[192][16];   // [(c*3+t)][f]
    __shared__ float swa[64][64];    // [c][o]
    __shared__ float swb[64];
    int b = blockIdx.x;
    int n = b / (LSEQ/TL);
    int l0 = (b % (LSEQ/TL)) * TL;
    int tid = threadIdx.x;

    for (int idx = tid; idx < (TL+2)*64; idx += 256){
        int r = idx >> 6, c = idx & 63;
        int l = l0 + r - 1;
        sx[r][c] = (l >= 0 && l < LSEQ) ? x[((size_t)n*LSEQ + l)*64 + c] : 0.f;
    }
    for (int idx = tid; idx < 3072; idx += 256){
        int f = idx / 192, rem = idx % 192;
        swm[rem][f] = wm[idx];
    }
    for (int idx = tid; idx < 4096; idx += 256){
        int o = idx >> 6, c = idx & 63;
        swa[c][o] = wa[idx];
    }
    if (tid < 64) swb[tid] = wb[tid];
    __syncthreads();

    for (int idx = tid; idx < TL*16; idx += 256){
        int lr = idx >> 4, f = idx & 15;
        float acc = 0.f;
        #pragma unroll 8
        for (int c = 0; c < 64; c++){
            acc = fmaf(sx[lr  ][c], swm[c*3+0][f], acc);
            acc = fmaf(sx[lr+1][c], swm[c*3+1][f], acc);
            acc = fmaf(sx[lr+2][c], swm[c*3+2][f], acc);
        }
        g_xembed[n][l0+lr][f] = acc;
    }
    for (int idx = tid; idx < TL*64; idx += 256){
        int lr = idx >> 6, o = idx & 63;
        float acc = swb[o];
        #pragma unroll 8
        for (int c = 0; c < 64; c++)
            acc = fmaf(sx[lr+1][c], swa[c][o], acc);
        g_yembed[n][l0+lr][o] = acc;
    }
}

// ---------------- K2: LSH codes + norms ----------------
#define TLH 64
__global__ void k_hash(const float* __restrict__ rot){
    __shared__ float sR[4][128][16];   // [h][i][f]
    __shared__ float sxe[TLH][17];
    int b = blockIdx.x;
    int n = b / (LSEQ/TLH);
    int l0 = (b % (LSEQ/TLH)) * TLH;
    int tid = threadIdx.x;

    for (int idx = tid; idx < 8192; idx += 256){
        int f = idx >> 9, h = (idx >> 7) & 3, i = idx & 127;
        sR[h][i][f] = rot[idx];
    }
    for (int idx = tid; idx < TLH*16; idx += 256){
        int ll = idx >> 4, f = idx & 15;
        sxe[ll][f] = g_xembed[n][l0+ll][f];
    }
    __syncthreads();

    int h = tid >> 6, ll = tid & 63;
    int l = l0 + ll;
    float q[16];
    #pragma unroll
    for (int f = 0; f < 16; f++) q[f] = sxe[ll][f];

    if (h == 0){
        float nn = 0.f;
        #pragma unroll
        for (int f = 0; f < 16; f++) nn = fmaf(q[f], q[f], nn);
        nn = sqrtf(nn);
        g_xnorm[n][l] = nn;
        g_invn[n][l]  = 1.f / fmaxf(nn, 5e-5f);
    }
    float m1 = -1e30f, m2 = 1e30f; int i1 = 0, i2 = 0;
    for (int i = 0; i < 128; i++){
        float v = 0.f;
        #pragma unroll
        for (int f = 0; f < 16; f++) v = fmaf(q[f], sR[h][i][f], v);
        if (v > m1){ m1 = v; i1 = i; }
        if (v < m2){ m2 = v; i2 = i; }
    }
    int code = (m1 >= -m2) ? i1 : (HB + i2);
    g_codes[n][h*LSEQ + l] = code + h*HB;
}

// ---------------- K3a: per-tile histograms ----------------
__global__ void k_hist(){
    __shared__ int hcnt[NKEY];
    int b = blockIdx.x; int n = b >> 7, tl = b & 127;
    int t = threadIdx.x;
    for (int kk = t; kk < NKEY; kk += TILE) hcnt[kk] = 0;
    __syncthreads();
    int key = g_codes[n][tl*TILE + t];
    atomicAdd(&hcnt[key], 1);
    __syncthreads();
    for (int kk = t; kk < NKEY; kk += TILE) g_tileHist[n][tl][kk] = hcnt[kk];
}

// ---------------- K3b: tile-prefix + key base ----------------
__global__ void k_scan(){
    __shared__ int stot[NKEY];
    int n = blockIdx.x; int k = threadIdx.x;
    if (k < NKEY){
        int run = 0;
        for (int tl = 0; tl < NTILE; tl++){
            int v = g_tileHist[n][tl][k];
            g_tileHist[n][tl][k] = run;
            run += v;
        }
        stot[k] = run;
    }
    __syncthreads();
    if (k == 0){
        int base = 0;
        for (int kk = 0; kk < NKEY; kk++){
            g_keyBase[n][kk] = base;
            base += stot[kk];
        }
    }
}

// ---------------- K3c: stable scatter ----------------
__global__ void k_scatter(){
    __shared__ int skey[TILE];
    int b = blockIdx.x; int n = b >> 7, tl = b & 127;
    int t = threadIdx.x;
    int key = g_codes[n][tl*TILE + t];
    skey[t] = key;
    __syncthreads();
    int r = 0;
    for (int u = 0; u < TILE; u++){
        int ku = skey[u];
        if (u < t && ku == key) r++;
    }
    int pos = g_keyBase[n][key] + g_tileHist[n][tl][key] + r;
    g_perm[n][pos] = tl*TILE + t;
}

// ---------------- K4: chunked attention ----------------
__global__ void __launch_bounds__(128) k_attn(){
    __shared__ __align__(16) float skey[128][20];
    __shared__ __align__(16) float sval[128][68];
    int cid = blockIdx.x;
    int n = cid >> 9, rem = cid & 511;
    int g = rem >> 7, k = rem & 127;
    int i = threadIdx.x;

    int p = (g << 14) + (k << 7) + i;
    int j = g_perm[n][p];
    int l = j & (LSEQ - 1);

    float q[16];
    const float4* qp = (const float4*)&g_xembed[n][l][0];
    #pragma unroll
    for (int t = 0; t < 4; t++){
        float4 v = qp[t];
        q[4*t] = v.x; q[4*t+1] = v.y; q[4*t+2] = v.z; q[4*t+3] = v.w;
    }
    ull q2[8];
    #pragma unroll
    for (int u = 0; u < 8; u++) q2[u] = pk2(q[2*u], q[2*u+1]);

    float m = g_xnorm[n][l];
    float s = 0.f;
    ull acc[32];
    #pragma unroll
    for (int u = 0; u < 32; u++) acc[u] = 0ull;

    for (int pass = 0; pass < 3; pass++){
        int kc = (pass == 0) ? k : (pass == 1) ? ((k + 127) & 127) : ((k + 1) & 127);
        __syncthreads();
        {
            int p2 = (g << 14) + (kc << 7) + i;
            int j2 = g_perm[n][p2];
            int l2 = j2 & (LSEQ - 1);
            float inv = g_invn[n][l2];
            const float4* kp = (const float4*)&g_xembed[n][l2][0];
            #pragma unroll
            for (int t = 0; t < 4; t++){
                float4 v = kp[t];
                v.x *= inv; v.y *= inv; v.z *= inv; v.w *= inv;
                *(float4*)&skey[i][4*t] = v;
            }
            const float4* vp = (const float4*)&g_yembed[n][l2][0];
            #pragma unroll
            for (int t = 0; t < 16; t++)
                *(float4*)&sval[i][4*t] = vp[t];
        }
        __syncthreads();

        for (int jj = 0; jj < 128; jj++){
            const ulonglong2* kk = (const ulonglong2*)&skey[jj][0];
            ull d = 0ull;
            #pragma unroll
            for (int t = 0; t < 4; t++){
                ulonglong2 kv = kk[t];
                d = f2fma(q2[2*t],   kv.x, d);
                d = f2fma(q2[2*t+1], kv.y, d);
            }
            float dx, dy; upk2(d, dx, dy);
            float e = fexp((dx + dy) - m);
            s += e;
            ull ee = pk2(e, e);
            const ulonglong2* vv = (const ulonglong2*)&sval[jj][0];
            #pragma unroll
            for (int t = 0; t < 16; t++){
                ulonglong2 v2 = vv[t];
                acc[2*t]   = f2fma(ee, v2.x, acc[2*t]);
                acc[2*t+1] = f2fma(ee, v2.y, acc[2*t+1]);
            }
        }
    }
    float rs = 1.f / s;
    float4* outp = (float4*)&g_ret[n][j][0];
    #pragma unroll
    for (int t = 0; t < 16; t++){
        float a, bb, c, d;
        upk2(acc[2*t],   a, bb);
        upk2(acc[2*t+1], c, d);
        float4 o; o.x = a*rs; o.y = bb*rs; o.z = c*rs; o.w = d*rs;
        outp[t] = o;
    }
    g_bs[n][j] = m + logf(s);
}

// ---------------- K5: softmax-over-hash combine + residual ----------------
__global__ void k_combine(const float* __restrict__ x, float* __restrict__ out){
    int gt = blockIdx.x * 256 + threadIdx.x;
    int n = gt >> 14, l = gt & (LSEQ - 1);
    float b0 = g_bs[n][l];
    float b1 = g_bs[n][LSEQ + l];
    float b2 = g_bs[n][2*LSEQ + l];
    float b3 = g_bs[n][3*LSEQ + l];
    float mx = fmaxf(fmaxf(b0, b1), fmaxf(b2, b3));
    float e0 = fexp(b0 - mx), e1 = fexp(b1 - mx), e2 = fexp(b2 - mx), e3 = fexp(b3 - mx);
    float inv = 1.f / (e0 + e1 + e2 + e3);
    float p0 = e0*inv, p1 = e1*inv, p2 = e2*inv, p3 = e3*inv;

    const float4* x4 = (const float4*)&x[((size_t)n*LSEQ + l)*64];
    const float4* r0 = (const float4*)&g_ret[n][l][0];
    const float4* r1 = (const float4*)&g_ret[n][LSEQ + l][0];
    const float4* r2 = (const float4*)&g_ret[n][2*LSEQ + l][0];
    const float4* r3 = (const float4*)&g_ret[n][3*LSEQ + l][0];
    float4* o4 = (float4*)&out[((size_t)n*LSEQ + l)*64];
    #pragma unroll
    for (int t = 0; t < 16; t++){
        float4 a = x4[t];
        float4 v0 = r0[t], v1 = r1[t], v2 = r2[t], v3 = r3[t];
        float4 o;
        o.x = a.x + p0*v0.x + p1*v1.x + p2*v2.x + p3*v3.x;
        o.y = a.y + p0*v0.y + p1*v1.y + p2*v2.y + p3*v3.y;
        o.z = a.z + p0*v0.z + p1*v1.z + p2*v2.z + p3*v3.z;
        o.w = a.w + p0*v0.w + p1*v1.w + p2*v2.w + p3*v3.w;
        o4[t] = o;
    }
}

// ---------------- launch ----------------
extern "C" void kernel_launch(void* const* d_in, const int* in_sizes, int n_in,
                              void* d_out, int out_size){
    const float* x  = (const float*)d_in[0];
    const float* wm = (const float*)d_in[1];
    const float* wa = (const float*)d_in[2];
    const float* wb = (const float*)d_in[3];
    const float* rt = (const float*)d_in[4];
    float* out = (float*)d_out;

    k_embed  <<<NB*(LSEQ/TL),  256>>>(x, wm, wa, wb);
    k_hash   <<<NB*(LSEQ/TLH), 256>>>(rt);
    k_hist   <<<NB*NTILE, TILE>>>();
    k_scan   <<<NB, 1024>>>();
    k_scatter<<<NB*NTILE, TILE>>>();
    k_attn   <<<NB*NH*KCH, 128>>>();
    k_combine<<<(NB*LSEQ)/256, 256>>>(x, out);
}